// round 6
// baseline (speedup 1.0000x reference)
#include <cuda_runtime.h>
#include <cstdint>

#define T_LEN 4096
#define IN_DIM 256
#define H_DIM 1024
#define G4H   4096
#define NCTA  128
#define UNITS 8     // hidden units per CTA (128 * 8 = 1024)

// ---------------- device scratch (static: no allocations allowed) ----------
__device__ float g_xz[(size_t)T_LEN * G4H];     // 64 MB: input projections
__device__ float g_hall[(size_t)T_LEN * H_DIM]; // 16 MB: h outputs of current layer
// Fused data+flag publish buffer: each entry = {tag : hi32, h_bits : lo32}.
// Written with a single 8B relaxed store => tag visibility == data visibility.
// Tag scheme: layer*(T_LEN+1) + t + 1 for step t, layer*(T_LEN+1) for h_{-1}.
// Consumers check EQUALITY, which is safe because:
//  - within a replay: leftover tags from layer l-1 are <= l*(T+1)-1 < any
//    layer-l expected tag;
//  - across graph replays: end-of-replay leftovers are layer-3 tags
//    (>= 3*(T+1)), never equal to early-layer expected tags; buffers are
//    overwritten monotonically within the replay before reuse;
//  - first run ever: zero-init slots have tag 0 == layer-0 h_{-1} tag with
//    value 0.0f, which is exactly the intended initial state.
__device__ unsigned long long g_htag[2][H_DIM];

// ---------------- memory-order helpers --------------------------------------
__device__ __forceinline__ unsigned long long ld_relaxed64(const unsigned long long* p) {
    unsigned long long v;
    asm volatile("ld.relaxed.gpu.global.b64 %0, [%1];" : "=l"(v) : "l"(p) : "memory");
    return v;
}
__device__ __forceinline__ void st_relaxed64(unsigned long long* p, unsigned long long v) {
    asm volatile("st.relaxed.gpu.global.b64 [%0], %1;" :: "l"(p), "l"(v) : "memory");
}

// ---------------- packed f32x2 FMA helper ----------------------------------
union F2u { float2 f; unsigned long long u; };

__device__ __forceinline__ void fma2(unsigned long long& d,
                                     unsigned long long a,
                                     unsigned long long b) {
    asm volatile("fma.rn.f32x2 %0, %1, %2, %0;" : "+l"(d) : "l"(a), "l"(b));
}

// ---------------- fast, overflow-safe activations ---------------------------
__device__ __forceinline__ float fast_sigmoid(float x) {
    return __fdividef(1.f, 1.f + __expf(-x));
}
__device__ __forceinline__ float fast_tanh(float x) {
    float a = fabsf(x);
    float e = __expf(-2.f * a);               // in (0, 1], never overflows
    float t = (1.f - e) * __fdividef(1.f, 1.f + e);
    return copysignf(t, x);
}

// ---------------- GEMM: xz = A @ W^T + bias --------------------------------
template<int K>
__global__ __launch_bounds__(256, 2)
void gemm_xz(const float* __restrict__ A_in,
             const float* __restrict__ W,
             const float* __restrict__ bias) {
    const float* A = A_in ? A_in : g_hall;   // nullptr => previous layer's h

    __shared__ float As[16][132];
    __shared__ float Bs[16][132];

    const int tid  = threadIdx.x;
    const int row0 = blockIdx.y * 128;
    const int col0 = blockIdx.x * 128;
    const int ty   = tid >> 4;
    const int tx   = tid & 15;

    float acc[8][8];
#pragma unroll
    for (int i = 0; i < 8; i++)
#pragma unroll
        for (int j = 0; j < 8; j++) acc[i][j] = 0.f;

    for (int k0 = 0; k0 < K; k0 += 16) {
#pragma unroll
        for (int i = 0; i < 2; i++) {
            int f  = tid + i * 256;
            int r  = f >> 2;
            int c4 = f & 3;
            float4 va = *(const float4*)(A + (size_t)(row0 + r) * K + k0 + c4 * 4);
            As[c4 * 4 + 0][r] = va.x;
            As[c4 * 4 + 1][r] = va.y;
            As[c4 * 4 + 2][r] = va.z;
            As[c4 * 4 + 3][r] = va.w;
            float4 vb = *(const float4*)(W + (size_t)(col0 + r) * K + k0 + c4 * 4);
            Bs[c4 * 4 + 0][r] = vb.x;
            Bs[c4 * 4 + 1][r] = vb.y;
            Bs[c4 * 4 + 2][r] = vb.z;
            Bs[c4 * 4 + 3][r] = vb.w;
        }
        __syncthreads();

#pragma unroll
        for (int k = 0; k < 16; k++) {
            float4 a0 = *(const float4*)&As[k][ty * 8];
            float4 a1 = *(const float4*)&As[k][ty * 8 + 4];
            float4 b0 = *(const float4*)&Bs[k][tx * 8];
            float4 b1 = *(const float4*)&Bs[k][tx * 8 + 4];
            float a[8] = {a0.x, a0.y, a0.z, a0.w, a1.x, a1.y, a1.z, a1.w};
            float b[8] = {b0.x, b0.y, b0.z, b0.w, b1.x, b1.y, b1.z, b1.w};
#pragma unroll
            for (int i = 0; i < 8; i++)
#pragma unroll
                for (int j = 0; j < 8; j++) acc[i][j] += a[i] * b[j];
        }
        __syncthreads();
    }

    float bj[8];
#pragma unroll
    for (int j = 0; j < 8; j++) bj[j] = bias[col0 + tx * 8 + j];

#pragma unroll
    for (int i = 0; i < 8; i++) {
        int r = row0 + ty * 8 + i;
#pragma unroll
        for (int j = 0; j < 8; j++) {
            g_xz[(size_t)r * G4H + col0 + tx * 8 + j] = acc[i][j] + bj[j];
        }
    }
}

// ---------------- recurrent scan -------------------------------------------
// 128 CTAs x 256 threads, all co-resident. CTA b owns hidden units [8b, 8b+8).
// W_hh slice (32 rows x 1024) lives in REGISTERS (128 floats/thread).
// Sync fabric: fused {tag,h} 64-bit publish, zero fences, zero atomics.
//   producer: 8 lanes st.relaxed.b64 {tag, h_bits}
//   consumer: thread tid watches slots 4tid..4tid+3; reloads only while its
//             tags are stale; CTA exits via __syncthreads_and.
__global__ __launch_bounds__(256, 1)
void lstm_scan(const float* __restrict__ Whh, int layer) {
    __shared__ float sh_h[H_DIM];
    __shared__ float sh_z[32];

    const int bid   = blockIdx.x;
    const int tid   = threadIdx.x;
    const int wid   = tid >> 5;
    const int lane  = tid & 31;
    const int ubase = bid * UNITS;

    // load this CTA's W_hh slice into registers.
    // warp w handles slice-rows s = 4w..4w+3, s -> (gate = s>>3, unit = s&7).
    float4 wreg[4][8];
#pragma unroll
    for (int j = 0; j < 4; j++) {
        int s    = wid * 4 + j;
        int gate = s >> 3;
        int unit = s & 7;
        const float4* wr =
            (const float4*)(Whh + ((size_t)gate * H_DIM + ubase + unit) * H_DIM);
#pragma unroll
        for (int c = 0; c < 8; c++) wreg[j][c] = wr[c * 32 + lane];
    }

    const unsigned tagbase = (unsigned)layer * (unsigned)(T_LEN + 1);
    float c_state = 0.f;   // meaningful for tid < 8 only

    // publish h_{-1} = 0 with tag = tagbase into the parity-1 buffer
    if (tid < UNITS) {
        st_relaxed64(&g_htag[1][ubase + tid], (unsigned long long)tagbase << 32);
    }

    for (int t = 0; t < T_LEN; t++) {
        // prefetch xz for this step (independent of h; overlaps the wait)
        float xzi = 0.f, xzf = 0.f, xzg = 0.f, xzo = 0.f;
        if (tid < UNITS) {
            const float* xz = g_xz + (size_t)t * G4H + ubase + tid;
            xzi = __ldg(xz);
            xzf = __ldg(xz + H_DIM);
            xzg = __ldg(xz + 2 * H_DIM);
            xzo = __ldg(xz + 3 * H_DIM);
        }

        // wait for h_{t-1}: thread tid watches 4 fused slots; the successful
        // load already contains the h payload (no second round trip).
        unsigned long long* buf = g_htag[(t + 1) & 1];
        const unsigned exp_tag  = tagbase + (unsigned)t;   // tag of h_{t-1}
        unsigned long long pr0 = 0, pr1 = 0, pr2 = 0, pr3 = 0;
        bool ok = false;
        do {
            if (!ok) {
                pr0 = ld_relaxed64(buf + 4 * tid + 0);
                pr1 = ld_relaxed64(buf + 4 * tid + 1);
                pr2 = ld_relaxed64(buf + 4 * tid + 2);
                pr3 = ld_relaxed64(buf + 4 * tid + 3);
                ok = ((unsigned)(pr0 >> 32) == exp_tag) &
                     ((unsigned)(pr1 >> 32) == exp_tag) &
                     ((unsigned)(pr2 >> 32) == exp_tag) &
                     ((unsigned)(pr3 >> 32) == exp_tag);
            }
        } while (!__syncthreads_and((int)ok));

        // stage h into shared (each thread contributes its 4 cached values)
        {
            float4 hv = make_float4(__uint_as_float((unsigned)pr0),
                                    __uint_as_float((unsigned)pr1),
                                    __uint_as_float((unsigned)pr2),
                                    __uint_as_float((unsigned)pr3));
            ((float4*)sh_h)[tid] = hv;
        }
        __syncthreads();                                   // (B)

        // packed dot products: 4 rows per warp, 32 cols per lane (conflict-free)
        unsigned long long acc[4];
        {
            F2u z; z.f = make_float2(0.f, 0.f);
            acc[0] = acc[1] = acc[2] = acc[3] = z.u;
        }
#pragma unroll
        for (int c = 0; c < 8; c++) {
            float4 hv = ((const float4*)sh_h)[c * 32 + lane];
            F2u hlo, hhi;
            hlo.f = make_float2(hv.x, hv.y);
            hhi.f = make_float2(hv.z, hv.w);
#pragma unroll
            for (int j = 0; j < 4; j++) {
                F2u wlo, whi;
                wlo.f = make_float2(wreg[j][c].x, wreg[j][c].y);
                whi.f = make_float2(wreg[j][c].z, wreg[j][c].w);
                fma2(acc[j], wlo.u, hlo.u);
                fma2(acc[j], whi.u, hhi.u);
            }
        }

        // 4 independent butterfly reductions, interleaved to pipeline
        float s0, s1, s2, s3;
        {
            F2u a0, a1, a2, a3;
            a0.u = acc[0]; a1.u = acc[1]; a2.u = acc[2]; a3.u = acc[3];
            s0 = a0.f.x + a0.f.y;
            s1 = a1.f.x + a1.f.y;
            s2 = a2.f.x + a2.f.y;
            s3 = a3.f.x + a3.f.y;
#pragma unroll
            for (int off = 16; off; off >>= 1) {
                s0 += __shfl_xor_sync(0xffffffffu, s0, off);
                s1 += __shfl_xor_sync(0xffffffffu, s1, off);
                s2 += __shfl_xor_sync(0xffffffffu, s2, off);
                s3 += __shfl_xor_sync(0xffffffffu, s3, off);
            }
        }
        if (lane == 0) {
            sh_z[wid * 4 + 0] = s0;
            sh_z[wid * 4 + 1] = s1;
            sh_z[wid * 4 + 2] = s2;
            sh_z[wid * 4 + 3] = s3;
        }
        __syncthreads();                                   // (C)

        // gates on threads 0..7; sh_z[u]=i, [8+u]=f, [16+u]=g, [24+u]=o
        if (tid < UNITS) {
            float zi = sh_z[tid]      + xzi;
            float zf = sh_z[8 + tid]  + xzf;
            float zg = sh_z[16 + tid] + xzg;
            float zo = sh_z[24 + tid] + xzo;
            float ig = fast_sigmoid(zi);
            float fg = fast_sigmoid(zf);
            float gg = fast_tanh(zg);
            float og = fast_sigmoid(zo);
            c_state  = fg * c_state + ig * gg;
            float h  = og * fast_tanh(c_state);
            unsigned long long pk =
                ((unsigned long long)(exp_tag + 1) << 32) |
                (unsigned long long)__float_as_uint(h);
            st_relaxed64(&g_htag[t & 1][ubase + tid], pk);  // fused publish
            g_hall[(size_t)t * H_DIM + ubase + tid] = h;    // consumed next launch
        }
        // no trailing barrier needed: the next step's poll loop starts with a
        // __syncthreads_and, and sh_h/sh_z overwrites sit behind it + (B).
    }
}

// ---------------- final FC: out[t][o] = hall[t] . fcW[o] + fcb[o] ----------
__global__ void fc_kernel(const float* __restrict__ W,
                          const float* __restrict__ b,
                          float* __restrict__ out) {
    int t    = blockIdx.x;
    int o    = threadIdx.x >> 5;   // 10 warps
    int lane = threadIdx.x & 31;
    const float4* h = (const float4*)(g_hall + (size_t)t * H_DIM);
    const float4* w = (const float4*)(W + (size_t)o * H_DIM);
    float s = 0.f;
#pragma unroll
    for (int c = 0; c < 8; c++) {
        float4 hv = h[c * 32 + lane];
        float4 wv = w[c * 32 + lane];
        s += hv.x * wv.x + hv.y * wv.y + hv.z * wv.z + hv.w * wv.w;
    }
#pragma unroll
    for (int off = 16; off; off >>= 1)
        s += __shfl_xor_sync(0xffffffffu, s, off);
    if (lane == 0) out[t * 10 + o] = s + b[o];
}

// ---------------- launch ----------------------------------------------------
extern "C" void kernel_launch(void* const* d_in, const int* in_sizes, int n_in,
                              void* d_out, int out_size) {
    const float* x     = (const float*)d_in[0];
    const float* Wih0  = (const float*)d_in[1];
    const float* Whh0  = (const float*)d_in[2];
    const float* b0    = (const float*)d_in[3];
    const float* WihR  = (const float*)d_in[4];
    const float* WhhR  = (const float*)d_in[5];
    const float* bR    = (const float*)d_in[6];
    const float* fcW   = (const float*)d_in[7];
    const float* fcb   = (const float*)d_in[8];
    float*       out   = (float*)d_out;

    dim3 ggrid(G4H / 128, T_LEN / 128);
    dim3 gblk(256);

    // layer 0
    gemm_xz<IN_DIM><<<ggrid, gblk>>>(x, Wih0, b0);
    lstm_scan<<<NCTA, 256>>>(Whh0, 0);

    // layers 1..3
    for (int l = 1; l < 4; l++) {
        const float* Wih = WihR + (size_t)(l - 1) * G4H * H_DIM;
        const float* Whh = WhhR + (size_t)(l - 1) * G4H * H_DIM;
        const float* bb  = bR   + (size_t)(l - 1) * G4H;
        gemm_xz<H_DIM><<<ggrid, gblk>>>(nullptr /* = g_hall */, Wih, bb);
        lstm_scan<<<NCTA, 256>>>(Whh, l);
    }

    fc_kernel<<<T_LEN, 320>>>(fcW, fcb, out);
}

// round 7
// speedup vs baseline: 1.1864x; 1.1864x over previous
#include <cuda_runtime.h>
#include <cstdint>

#define T_LEN 4096
#define IN_DIM 256
#define H_DIM 1024
#define G4H   4096
#define NCTA  128
#define UNITS 8     // hidden units per CTA (128 * 8 = 1024)
#define NREP  4     // publish-buffer replicas (slice de-amplification)

// ---------------- device scratch (static: no allocations allowed) ----------
__device__ float g_xz[(size_t)T_LEN * G4H];     // 64 MB: input projections
__device__ float g_hall[(size_t)T_LEN * H_DIM]; // 16 MB: h outputs of current layer
// Fused data+flag publish buffers, replicated NREP x to spread L2-slice load:
// entry = {tag : hi32, h_bits : lo32}, single 8B relaxed store per entry.
// Tag scheme: layer*(T_LEN+1) + t + 1 for step t, layer*(T_LEN+1) for h_{-1}.
// Equality-checked; replay-safe (see R6 analysis: stale tags never collide).
__device__ unsigned long long g_pub[2][NREP][H_DIM];

// ---------------- memory-order helpers --------------------------------------
__device__ __forceinline__ unsigned long long ld_relaxed64(const unsigned long long* p) {
    unsigned long long v;
    asm volatile("ld.relaxed.gpu.global.b64 %0, [%1];" : "=l"(v) : "l"(p) : "memory");
    return v;
}
__device__ __forceinline__ void st_relaxed64(unsigned long long* p, unsigned long long v) {
    asm volatile("st.relaxed.gpu.global.b64 [%0], %1;" :: "l"(p), "l"(v) : "memory");
}

// ---------------- packed f32x2 FMA helper ----------------------------------
union F2u { float2 f; unsigned long long u; };

__device__ __forceinline__ void fma2(unsigned long long& d,
                                     unsigned long long a,
                                     unsigned long long b) {
    asm volatile("fma.rn.f32x2 %0, %1, %2, %0;" : "+l"(d) : "l"(a), "l"(b));
}

// ---------------- fast, overflow-safe activations ---------------------------
__device__ __forceinline__ float fast_sigmoid(float x) {
    return __fdividef(1.f, 1.f + __expf(-x));
}
__device__ __forceinline__ float fast_tanh(float x) {
    float a = fabsf(x);
    float e = __expf(-2.f * a);               // in (0, 1], never overflows
    float t = (1.f - e) * __fdividef(1.f, 1.f + e);
    return copysignf(t, x);
}

// ---------------- GEMM: xz = A @ W^T + bias --------------------------------
template<int K>
__global__ __launch_bounds__(256, 2)
void gemm_xz(const float* __restrict__ A_in,
             const float* __restrict__ W,
             const float* __restrict__ bias) {
    const float* A = A_in ? A_in : g_hall;   // nullptr => previous layer's h

    __shared__ float As[16][132];
    __shared__ float Bs[16][132];

    const int tid  = threadIdx.x;
    const int row0 = blockIdx.y * 128;
    const int col0 = blockIdx.x * 128;
    const int ty   = tid >> 4;
    const int tx   = tid & 15;

    float acc[8][8];
#pragma unroll
    for (int i = 0; i < 8; i++)
#pragma unroll
        for (int j = 0; j < 8; j++) acc[i][j] = 0.f;

    for (int k0 = 0; k0 < K; k0 += 16) {
#pragma unroll
        for (int i = 0; i < 2; i++) {
            int f  = tid + i * 256;
            int r  = f >> 2;
            int c4 = f & 3;
            float4 va = *(const float4*)(A + (size_t)(row0 + r) * K + k0 + c4 * 4);
            As[c4 * 4 + 0][r] = va.x;
            As[c4 * 4 + 1][r] = va.y;
            As[c4 * 4 + 2][r] = va.z;
            As[c4 * 4 + 3][r] = va.w;
            float4 vb = *(const float4*)(W + (size_t)(col0 + r) * K + k0 + c4 * 4);
            Bs[c4 * 4 + 0][r] = vb.x;
            Bs[c4 * 4 + 1][r] = vb.y;
            Bs[c4 * 4 + 2][r] = vb.z;
            Bs[c4 * 4 + 3][r] = vb.w;
        }
        __syncthreads();

#pragma unroll
        for (int k = 0; k < 16; k++) {
            float4 a0 = *(const float4*)&As[k][ty * 8];
            float4 a1 = *(const float4*)&As[k][ty * 8 + 4];
            float4 b0 = *(const float4*)&Bs[k][tx * 8];
            float4 b1 = *(const float4*)&Bs[k][tx * 8 + 4];
            float a[8] = {a0.x, a0.y, a0.z, a0.w, a1.x, a1.y, a1.z, a1.w};
            float b[8] = {b0.x, b0.y, b0.z, b0.w, b1.x, b1.y, b1.z, b1.w};
#pragma unroll
            for (int i = 0; i < 8; i++)
#pragma unroll
                for (int j = 0; j < 8; j++) acc[i][j] += a[i] * b[j];
        }
        __syncthreads();
    }

    float bj[8];
#pragma unroll
    for (int j = 0; j < 8; j++) bj[j] = bias[col0 + tx * 8 + j];

#pragma unroll
    for (int i = 0; i < 8; i++) {
        int r = row0 + ty * 8 + i;
#pragma unroll
        for (int j = 0; j < 8; j++) {
            g_xz[(size_t)r * G4H + col0 + tx * 8 + j] = acc[i][j] + bj[j];
        }
    }
}

// ---------------- recurrent scan -------------------------------------------
// 128 CTAs x 256 threads, all co-resident. CTA b owns hidden units [8b, 8b+8).
// W_hh slice (32 rows x 1024) lives in REGISTERS (128 floats/thread).
// Sync fabric: fused {tag,h} 64-bit publish, replicated 4x.
//   producer lane u: 4 st.relaxed.b64 (one per replica)
//   consumer: CTA b polls replica (b & 3); thread tid watches 4 slots; the
//             successful load already carries the h payload.
__global__ __launch_bounds__(256, 1)
void lstm_scan(const float* __restrict__ Whh, int layer) {
    __shared__ float sh_h[H_DIM];
    __shared__ float sh_z[32];

    const int bid   = blockIdx.x;
    const int tid   = threadIdx.x;
    const int wid   = tid >> 5;
    const int lane  = tid & 31;
    const int ubase = bid * UNITS;
    const int rep   = bid & (NREP - 1);

    // load this CTA's W_hh slice into registers.
    // warp w handles slice-rows s = 4w..4w+3, s -> (gate = s>>3, unit = s&7).
    float4 wreg[4][8];
#pragma unroll
    for (int j = 0; j < 4; j++) {
        int s    = wid * 4 + j;
        int gate = s >> 3;
        int unit = s & 7;
        const float4* wr =
            (const float4*)(Whh + ((size_t)gate * H_DIM + ubase + unit) * H_DIM);
#pragma unroll
        for (int c = 0; c < 8; c++) wreg[j][c] = wr[c * 32 + lane];
    }

    const unsigned tagbase = (unsigned)layer * (unsigned)(T_LEN + 1);
    float c_state = 0.f;   // meaningful for tid < 8 only

    // publish h_{-1} = 0 with tag = tagbase into the parity-1 buffers
    if (tid < UNITS) {
        unsigned long long pk = (unsigned long long)tagbase << 32;
#pragma unroll
        for (int r = 0; r < NREP; r++)
            st_relaxed64(&g_pub[1][r][ubase + tid], pk);
    }

    for (int t = 0; t < T_LEN; t++) {
        // prefetch xz for this step (independent of h; overlaps the wait)
        float xzi = 0.f, xzf = 0.f, xzg = 0.f, xzo = 0.f;
        if (tid < UNITS) {
            const float* xz = g_xz + (size_t)t * G4H + ubase + tid;
            xzi = __ldg(xz);
            xzf = __ldg(xz + H_DIM);
            xzg = __ldg(xz + 2 * H_DIM);
            xzo = __ldg(xz + 3 * H_DIM);
        }

        // wait for h_{t-1}: thread tid watches 4 fused slots of OUR replica.
        unsigned long long* buf = g_pub[(t + 1) & 1][rep];
        const unsigned exp_tag  = tagbase + (unsigned)t;   // tag of h_{t-1}
        unsigned long long pr0 = 0, pr1 = 0, pr2 = 0, pr3 = 0;
        bool ok = false;
        do {
            if (!ok) {
                pr0 = ld_relaxed64(buf + 4 * tid + 0);
                pr1 = ld_relaxed64(buf + 4 * tid + 1);
                pr2 = ld_relaxed64(buf + 4 * tid + 2);
                pr3 = ld_relaxed64(buf + 4 * tid + 3);
                ok = ((unsigned)(pr0 >> 32) == exp_tag) &
                     ((unsigned)(pr1 >> 32) == exp_tag) &
                     ((unsigned)(pr2 >> 32) == exp_tag) &
                     ((unsigned)(pr3 >> 32) == exp_tag);
            }
        } while (!__syncthreads_and((int)ok));

        // stage h into shared (each thread contributes its 4 cached values)
        {
            float4 hv = make_float4(__uint_as_float((unsigned)pr0),
                                    __uint_as_float((unsigned)pr1),
                                    __uint_as_float((unsigned)pr2),
                                    __uint_as_float((unsigned)pr3));
            ((float4*)sh_h)[tid] = hv;
        }
        __syncthreads();                                   // (B)

        // packed dot products: 4 rows per warp, 32 cols per lane (conflict-free)
        unsigned long long acc[4];
        {
            F2u z; z.f = make_float2(0.f, 0.f);
            acc[0] = acc[1] = acc[2] = acc[3] = z.u;
        }
#pragma unroll
        for (int c = 0; c < 8; c++) {
            float4 hv = ((const float4*)sh_h)[c * 32 + lane];
            F2u hlo, hhi;
            hlo.f = make_float2(hv.x, hv.y);
            hhi.f = make_float2(hv.z, hv.w);
#pragma unroll
            for (int j = 0; j < 4; j++) {
                F2u wlo, whi;
                wlo.f = make_float2(wreg[j][c].x, wreg[j][c].y);
                whi.f = make_float2(wreg[j][c].z, wreg[j][c].w);
                fma2(acc[j], wlo.u, hlo.u);
                fma2(acc[j], whi.u, hhi.u);
            }
        }

        // 4 independent butterfly reductions, interleaved to pipeline
        float s0, s1, s2, s3;
        {
            F2u a0, a1, a2, a3;
            a0.u = acc[0]; a1.u = acc[1]; a2.u = acc[2]; a3.u = acc[3];
            s0 = a0.f.x + a0.f.y;
            s1 = a1.f.x + a1.f.y;
            s2 = a2.f.x + a2.f.y;
            s3 = a3.f.x + a3.f.y;
#pragma unroll
            for (int off = 16; off; off >>= 1) {
                s0 += __shfl_xor_sync(0xffffffffu, s0, off);
                s1 += __shfl_xor_sync(0xffffffffu, s1, off);
                s2 += __shfl_xor_sync(0xffffffffu, s2, off);
                s3 += __shfl_xor_sync(0xffffffffu, s3, off);
            }
        }
        if (lane == 0) {
            sh_z[wid * 4 + 0] = s0;
            sh_z[wid * 4 + 1] = s1;
            sh_z[wid * 4 + 2] = s2;
            sh_z[wid * 4 + 3] = s3;
        }
        __syncthreads();                                   // (C)

        // gates on threads 0..7; sh_z[u]=i, [8+u]=f, [16+u]=g, [24+u]=o
        if (tid < UNITS) {
            float zi = sh_z[tid]      + xzi;
            float zf = sh_z[8 + tid]  + xzf;
            float zg = sh_z[16 + tid] + xzg;
            float zo = sh_z[24 + tid] + xzo;
            float ig = fast_sigmoid(zi);
            float fg = fast_sigmoid(zf);
            float gg = fast_tanh(zg);
            float og = fast_sigmoid(zo);
            c_state  = fg * c_state + ig * gg;
            float h  = og * fast_tanh(c_state);
            unsigned long long pk =
                ((unsigned long long)(exp_tag + 1) << 32) |
                (unsigned long long)__float_as_uint(h);
            unsigned long long* dst = &g_pub[t & 1][0][ubase + tid];
#pragma unroll
            for (int r = 0; r < NREP; r++)
                st_relaxed64(dst + (size_t)r * H_DIM, pk); // fused publish x4
            g_hall[(size_t)t * H_DIM + ubase + tid] = h;   // consumed next launch
        }
        // no trailing barrier needed: the next step's poll loop starts with a
        // __syncthreads_and, and sh_h/sh_z overwrites sit behind it + (B).
    }
}

// ---------------- final FC: out[t][o] = hall[t] . fcW[o] + fcb[o] ----------
__global__ void fc_kernel(const float* __restrict__ W,
                          const float* __restrict__ b,
                          float* __restrict__ out) {
    int t    = blockIdx.x;
    int o    = threadIdx.x >> 5;   // 10 warps
    int lane = threadIdx.x & 31;
    const float4* h = (const float4*)(g_hall + (size_t)t * H_DIM);
    const float4* w = (const float4*)(W + (size_t)o * H_DIM);
    float s = 0.f;
#pragma unroll
    for (int c = 0; c < 8; c++) {
        float4 hv = h[c * 32 + lane];
        float4 wv = w[c * 32 + lane];
        s += hv.x * wv.x + hv.y * wv.y + hv.z * wv.z + hv.w * wv.w;
    }
#pragma unroll
    for (int off = 16; off; off >>= 1)
        s += __shfl_xor_sync(0xffffffffu, s, off);
    if (lane == 0) out[t * 10 + o] = s + b[o];
}

// ---------------- launch ----------------------------------------------------
extern "C" void kernel_launch(void* const* d_in, const int* in_sizes, int n_in,
                              void* d_out, int out_size) {
    const float* x     = (const float*)d_in[0];
    const float* Wih0  = (const float*)d_in[1];
    const float* Whh0  = (const float*)d_in[2];
    const float* b0    = (const float*)d_in[3];
    const float* WihR  = (const float*)d_in[4];
    const float* WhhR  = (const float*)d_in[5];
    const float* bR    = (const float*)d_in[6];
    const float* fcW   = (const float*)d_in[7];
    const float* fcb   = (const float*)d_in[8];
    float*       out   = (float*)d_out;

    dim3 ggrid(G4H / 128, T_LEN / 128);
    dim3 gblk(256);

    // layer 0
    gemm_xz<IN_DIM><<<ggrid, gblk>>>(x, Wih0, b0);
    lstm_scan<<<NCTA, 256>>>(Whh0, 0);

    // layers 1..3
    for (int l = 1; l < 4; l++) {
        const float* Wih = WihR + (size_t)(l - 1) * G4H * H_DIM;
        const float* Whh = WhhR + (size_t)(l - 1) * G4H * H_DIM;
        const float* bb  = bR   + (size_t)(l - 1) * G4H;
        gemm_xz<H_DIM><<<ggrid, gblk>>>(nullptr /* = g_hall */, Wih, bb);
        lstm_scan<<<NCTA, 256>>>(Whh, l);
    }

    fc_kernel<<<T_LEN, 320>>>(fcW, fcb, out);
}

// round 8
// speedup vs baseline: 1.3529x; 1.1403x over previous
#include <cuda_runtime.h>
#include <cstdint>

#define T_LEN 4096
#define IN_DIM 256
#define H_DIM 1024
#define G4H   4096
#define NCTA  128
#define UNITS 8     // hidden units per CTA (128 * 8 = 1024)
#define NREP  4     // publish-buffer replicas (slice de-amplification)

// ---------------- device scratch (static: no allocations allowed) ----------
__device__ float g_xz[(size_t)T_LEN * G4H];     // 64 MB: input projections
__device__ float g_hall[(size_t)T_LEN * H_DIM]; // 16 MB: h outputs of current layer
// Fused data+flag publish buffers, replicated NREP x to spread L2-slice load:
// entry = {tag : hi32, h_bits : lo32}, single 8B relaxed store per entry.
// Tag = layer*(T_LEN+1) + t + 1 for step t; layer*(T_LEN+1) for h_{-1}.
// Equality-checked; replay-safe (stale tags from other layers/replays never
// equal the expected tag; zero-init == layer-0 h_{-1} with value 0).
__device__ unsigned long long g_pub[2][NREP][H_DIM];

// ---------------- memory-order helpers --------------------------------------
__device__ __forceinline__ unsigned long long ld_relaxed64(const unsigned long long* p) {
    unsigned long long v;
    asm volatile("ld.relaxed.gpu.global.b64 %0, [%1];" : "=l"(v) : "l"(p) : "memory");
    return v;
}
__device__ __forceinline__ void st_relaxed64(unsigned long long* p, unsigned long long v) {
    asm volatile("st.relaxed.gpu.global.b64 [%0], %1;" :: "l"(p), "l"(v) : "memory");
}

// ---------------- packed f32x2 FMA helper ----------------------------------
union F2u { float2 f; unsigned long long u; };

__device__ __forceinline__ void fma2(unsigned long long& d,
                                     unsigned long long a,
                                     unsigned long long b) {
    asm volatile("fma.rn.f32x2 %0, %1, %2, %0;" : "+l"(d) : "l"(a), "l"(b));
}

// ---------------- fast, overflow-safe activations ---------------------------
__device__ __forceinline__ float fast_sigmoid(float x) {
    return __fdividef(1.f, 1.f + __expf(-x));
}
__device__ __forceinline__ float fast_tanh(float x) {
    float a = fabsf(x);
    float e = __expf(-2.f * a);               // in (0, 1], never overflows
    float t = (1.f - e) * __fdividef(1.f, 1.f + e);
    return copysignf(t, x);
}

// ---------------- GEMM: xz = A @ W^T + bias --------------------------------
template<int K>
__global__ __launch_bounds__(256, 2)
void gemm_xz(const float* __restrict__ A_in,
             const float* __restrict__ W,
             const float* __restrict__ bias) {
    const float* A = A_in ? A_in : g_hall;   // nullptr => previous layer's h

    __shared__ float As[16][132];
    __shared__ float Bs[16][132];

    const int tid  = threadIdx.x;
    const int row0 = blockIdx.y * 128;
    const int col0 = blockIdx.x * 128;
    const int ty   = tid >> 4;
    const int tx   = tid & 15;

    float acc[8][8];
#pragma unroll
    for (int i = 0; i < 8; i++)
#pragma unroll
        for (int j = 0; j < 8; j++) acc[i][j] = 0.f;

    for (int k0 = 0; k0 < K; k0 += 16) {
#pragma unroll
        for (int i = 0; i < 2; i++) {
            int f  = tid + i * 256;
            int r  = f >> 2;
            int c4 = f & 3;
            float4 va = *(const float4*)(A + (size_t)(row0 + r) * K + k0 + c4 * 4);
            As[c4 * 4 + 0][r] = va.x;
            As[c4 * 4 + 1][r] = va.y;
            As[c4 * 4 + 2][r] = va.z;
            As[c4 * 4 + 3][r] = va.w;
            float4 vb = *(const float4*)(W + (size_t)(col0 + r) * K + k0 + c4 * 4);
            Bs[c4 * 4 + 0][r] = vb.x;
            Bs[c4 * 4 + 1][r] = vb.y;
            Bs[c4 * 4 + 2][r] = vb.z;
            Bs[c4 * 4 + 3][r] = vb.w;
        }
        __syncthreads();

#pragma unroll
        for (int k = 0; k < 16; k++) {
            float4 a0 = *(const float4*)&As[k][ty * 8];
            float4 a1 = *(const float4*)&As[k][ty * 8 + 4];
            float4 b0 = *(const float4*)&Bs[k][tx * 8];
            float4 b1 = *(const float4*)&Bs[k][tx * 8 + 4];
            float a[8] = {a0.x, a0.y, a0.z, a0.w, a1.x, a1.y, a1.z, a1.w};
            float b[8] = {b0.x, b0.y, b0.z, b0.w, b1.x, b1.y, b1.z, b1.w};
#pragma unroll
            for (int i = 0; i < 8; i++)
#pragma unroll
                for (int j = 0; j < 8; j++) acc[i][j] += a[i] * b[j];
        }
        __syncthreads();
    }

    float bj[8];
#pragma unroll
    for (int j = 0; j < 8; j++) bj[j] = bias[col0 + tx * 8 + j];

#pragma unroll
    for (int i = 0; i < 8; i++) {
        int r = row0 + ty * 8 + i;
#pragma unroll
        for (int j = 0; j < 8; j++) {
            g_xz[(size_t)r * G4H + col0 + tx * 8 + j] = acc[i][j] + bj[j];
        }
    }
}

// ---------------- recurrent scan -------------------------------------------
// 128 CTAs x 256 threads, all co-resident. CTA b owns hidden units [8b, 8b+8).
// W_hh slice (32 rows x 1024) lives in REGISTERS (128 floats/thread).
// Sync fabric: fused {tag,h} 64-bit publish, replicated 4x.
//   producer lane u: NREP st.relaxed.b64
//   consumer: each thread spins INDEPENDENTLY on its own 4 slots (stops
//   loading once tagged), stages its h values to smem, then one barrier.
__global__ __launch_bounds__(256, 1)
void lstm_scan(const float* __restrict__ Whh, int layer) {
    __shared__ float sh_h[H_DIM];
    __shared__ float sh_z[32];

    const int bid   = blockIdx.x;
    const int tid   = threadIdx.x;
    const int wid   = tid >> 5;
    const int lane  = tid & 31;
    const int ubase = bid * UNITS;
    const int rep   = bid & (NREP - 1);

    // load this CTA's W_hh slice into registers.
    // warp w handles slice-rows s = 4w..4w+3, s -> (gate = s>>3, unit = s&7).
    float4 wreg[4][8];
#pragma unroll
    for (int j = 0; j < 4; j++) {
        int s    = wid * 4 + j;
        int gate = s >> 3;
        int unit = s & 7;
        const float4* wr =
            (const float4*)(Whh + ((size_t)gate * H_DIM + ubase + unit) * H_DIM);
#pragma unroll
        for (int c = 0; c < 8; c++) wreg[j][c] = wr[c * 32 + lane];
    }

    const unsigned tagbase = (unsigned)layer * (unsigned)(T_LEN + 1);
    float c_state = 0.f;   // meaningful for tid < 8 only

    // publish h_{-1} = 0 with tag = tagbase into the parity-1 buffers
    if (tid < UNITS) {
        unsigned long long pk = (unsigned long long)tagbase << 32;
#pragma unroll
        for (int r = 0; r < NREP; r++)
            st_relaxed64(&g_pub[1][r][ubase + tid], pk);
    }

    for (int t = 0; t < T_LEN; t++) {
        // prefetch xz for this step (independent of h; overlaps the wait)
        float xzi = 0.f, xzf = 0.f, xzg = 0.f, xzo = 0.f;
        if (tid < UNITS) {
            const float* xz = g_xz + (size_t)t * G4H + ubase + tid;
            xzi = __ldg(xz);
            xzf = __ldg(xz + H_DIM);
            xzg = __ldg(xz + 2 * H_DIM);
            xzo = __ldg(xz + 3 * H_DIM);
        }

        // wait for h_{t-1}: thread tid watches 4 fused slots of OUR replica,
        // spinning independently; once its slots are tagged it stops loading.
        {
            unsigned long long* buf = g_pub[(t + 1) & 1][rep];
            const unsigned exp_tag  = tagbase + (unsigned)t;   // tag of h_{t-1}
            unsigned long long pr0, pr1, pr2, pr3;
            int tries = 0;
            for (;;) {
                pr0 = ld_relaxed64(buf + 4 * tid + 0);
                pr1 = ld_relaxed64(buf + 4 * tid + 1);
                pr2 = ld_relaxed64(buf + 4 * tid + 2);
                pr3 = ld_relaxed64(buf + 4 * tid + 3);
                bool ok = ((unsigned)(pr0 >> 32) == exp_tag) &
                          ((unsigned)(pr1 >> 32) == exp_tag) &
                          ((unsigned)(pr2 >> 32) == exp_tag) &
                          ((unsigned)(pr3 >> 32) == exp_tag);
                if (ok) break;
                if (++tries > 2) __nanosleep(40);   // back off the hot line
            }
            // stage own h values; the single barrier below covers both
            // "all slots observed" and "smem staged".
            ((float4*)sh_h)[tid] =
                make_float4(__uint_as_float((unsigned)pr0),
                            __uint_as_float((unsigned)pr1),
                            __uint_as_float((unsigned)pr2),
                            __uint_as_float((unsigned)pr3));
        }
        __syncthreads();                                   // (B)

        // packed dot products: 4 rows per warp, 32 cols per lane (conflict-free)
        unsigned long long acc[4];
        {
            F2u z; z.f = make_float2(0.f, 0.f);
            acc[0] = acc[1] = acc[2] = acc[3] = z.u;
        }
#pragma unroll
        for (int c = 0; c < 8; c++) {
            float4 hv = ((const float4*)sh_h)[c * 32 + lane];
            F2u hlo, hhi;
            hlo.f = make_float2(hv.x, hv.y);
            hhi.f = make_float2(hv.z, hv.w);
#pragma unroll
            for (int j = 0; j < 4; j++) {
                F2u wlo, whi;
                wlo.f = make_float2(wreg[j][c].x, wreg[j][c].y);
                whi.f = make_float2(wreg[j][c].z, wreg[j][c].w);
                fma2(acc[j], wlo.u, hlo.u);
                fma2(acc[j], whi.u, hhi.u);
            }
        }

        // 4 independent butterfly reductions, interleaved to pipeline
        float s0, s1, s2, s3;
        {
            F2u a0, a1, a2, a3;
            a0.u = acc[0]; a1.u = acc[1]; a2.u = acc[2]; a3.u = acc[3];
            s0 = a0.f.x + a0.f.y;
            s1 = a1.f.x + a1.f.y;
            s2 = a2.f.x + a2.f.y;
            s3 = a3.f.x + a3.f.y;
#pragma unroll
            for (int off = 16; off; off >>= 1) {
                s0 += __shfl_xor_sync(0xffffffffu, s0, off);
                s1 += __shfl_xor_sync(0xffffffffu, s1, off);
                s2 += __shfl_xor_sync(0xffffffffu, s2, off);
                s3 += __shfl_xor_sync(0xffffffffu, s3, off);
            }
        }
        if (lane == 0) {
            sh_z[wid * 4 + 0] = s0;
            sh_z[wid * 4 + 1] = s1;
            sh_z[wid * 4 + 2] = s2;
            sh_z[wid * 4 + 3] = s3;
        }
        __syncthreads();                                   // (C)

        // gates on threads 0..7; sh_z[u]=i, [8+u]=f, [16+u]=g, [24+u]=o
        if (tid < UNITS) {
            float zi = sh_z[tid]      + xzi;
            float zf = sh_z[8 + tid]  + xzf;
            float zg = sh_z[16 + tid] + xzg;
            float zo = sh_z[24 + tid] + xzo;
            float ig = fast_sigmoid(zi);
            float fg = fast_sigmoid(zf);
            float gg = fast_tanh(zg);
            float og = fast_sigmoid(zo);
            c_state  = fg * c_state + ig * gg;
            float h  = og * fast_tanh(c_state);
            unsigned long long pk =
                ((unsigned long long)(tagbase + (unsigned)t + 1u) << 32) |
                (unsigned long long)__float_as_uint(h);
            unsigned long long* dst = &g_pub[t & 1][0][ubase + tid];
#pragma unroll
            for (int r = 0; r < NREP; r++)
                st_relaxed64(dst + (size_t)r * H_DIM, pk); // fused publish x4
            g_hall[(size_t)t * H_DIM + ubase + tid] = h;   // consumed next launch
        }
        // smem hazards at t+1: sh_h overwrite happens after each thread's own
        // spin; any thread reaching that point has passed (C) at t, so no
        // thread can still be reading sh_h in the t-dot (pre-(C)). sh_z
        // overwrite at t+1 is post-(B@t+1), which warp 0 reaches only after
        // gates(t). Safe with 2 barriers/step.
    }
}

// ---------------- final FC: out[t][o] = hall[t] . fcW[o] + fcb[o] ----------
__global__ void fc_kernel(const float* __restrict__ W,
                          const float* __restrict__ b,
                          float* __restrict__ out) {
    int t    = blockIdx.x;
    int o    = threadIdx.x >> 5;   // 10 warps
    int lane = threadIdx.x & 31;
    const float4* h = (const float4*)(g_hall + (size_t)t * H_DIM);
    const float4* w = (const float4*)(W + (size_t)o * H_DIM);
    float s = 0.f;
#pragma unroll
    for (int c = 0; c < 8; c++) {
        float4 hv = h[c * 32 + lane];
        float4 wv = w[c * 32 + lane];
        s += hv.x * wv.x + hv.y * wv.y + hv.z * wv.z + hv.w * wv.w;
    }
#pragma unroll
    for (int off = 16; off; off >>= 1)
        s += __shfl_xor_sync(0xffffffffu, s, off);
    if (lane == 0) out[t * 10 + o] = s + b[o];
}

// ---------------- launch ----------------------------------------------------
extern "C" void kernel_launch(void* const* d_in, const int* in_sizes, int n_in,
                              void* d_out, int out_size) {
    const float* x     = (const float*)d_in[0];
    const float* Wih0  = (const float*)d_in[1];
    const float* Whh0  = (const float*)d_in[2];
    const float* b0    = (const float*)d_in[3];
    const float* WihR  = (const float*)d_in[4];
    const float* WhhR  = (const float*)d_in[5];
    const float* bR    = (const float*)d_in[6];
    const float* fcW   = (const float*)d_in[7];
    const float* fcb   = (const float*)d_in[8];
    float*       out   = (float*)d_out;

    dim3 ggrid(G4H / 128, T_LEN / 128);
    dim3 gblk(256);

    // layer 0
    gemm_xz<IN_DIM><<<ggrid, gblk>>>(x, Wih0, b0);
    lstm_scan<<<NCTA, 256>>>(Whh0, 0);

    // layers 1..3
    for (int l = 1; l < 4; l++) {
        const float* Wih = WihR + (size_t)(l - 1) * G4H * H_DIM;
        const float* Whh = WhhR + (size_t)(l - 1) * G4H * H_DIM;
        const float* bb  = bR   + (size_t)(l - 1) * G4H;
        gemm_xz<H_DIM><<<ggrid, gblk>>>(nullptr /* = g_hall */, Wih, bb);
        lstm_scan<<<NCTA, 256>>>(Whh, l);
    }

    fc_kernel<<<T_LEN, 320>>>(fcW, fcb, out);
}